// round 16
// baseline (speedup 1.0000x reference)
#include <cuda_runtime.h>
#include <cuda_fp16.h>
#include <cstdint>

#define MAX_NODES 100000
#define MAX_EDGES 1600000
#define IN_C  32
#define HID_C 64
#define OUT_C 32
#define NT 128
#define STRIDE 132
#define SCAN_CHUNK 1024
#define MAX_CHUNKS 128

// Scratch (__device__ globals: allocation-free rule)
__device__ __align__(16) float  g_agg1[MAX_NODES * IN_C];   // raw sums (fp32)
__device__ __align__(16) __half g_x16 [MAX_NODES * IN_C];   // x in fp16
__device__ __align__(16) __half g_hw16[MAX_NODES * OUT_C];  // relu(h)@W2l in fp16
__device__ int g_deg   [MAX_NODES];
__device__ int g_rowptr[MAX_NODES + 1];
__device__ int g_rank  [MAX_EDGES];
__device__ int g_col   [MAX_EDGES];
__device__ int g_chunkSum[MAX_CHUNKS];

// ---------------------------------------------------------------------------
// Packed f32x2 helpers (Blackwell FFMA2)
// ---------------------------------------------------------------------------
__device__ __forceinline__ void fma2(unsigned long long& d,
                                     unsigned long long a,
                                     unsigned long long b)
{
    asm("fma.rn.f32x2 %0, %1, %2, %0;" : "+l"(d) : "l"(a), "l"(b));
}
__device__ __forceinline__ unsigned long long pack2(float v)
{
    unsigned long long r;
    asm("mov.b64 %0, {%1, %1};" : "=l"(r) : "r"(__float_as_uint(v)));
    return r;
}
__device__ __forceinline__ float2 unpack2(unsigned long long v)
{
    float2 f;
    asm("mov.b64 {%0, %1}, %2;" : "=f"(f.x), "=f"(f.y) : "l"(v));
    return f;
}
__device__ __forceinline__ unsigned int h2u(__half2 h)
{
    return *reinterpret_cast<unsigned int*>(&h);
}

// ---------------------------------------------------------------------------
// x (fp32) -> x16 (fp16). 8 floats per thread.
// ---------------------------------------------------------------------------
__global__ void cvt_x16(const float* __restrict__ x, __half* __restrict__ x16,
                        int n8)   // n8 = n_nodes*IN_C/8
{
    int t = blockIdx.x * blockDim.x + threadIdx.x;
    if (t >= n8) return;
    const float4* p = (const float4*)x + t * 2;
    float4 a = p[0], b = p[1];
    uint4 o;
    o.x = h2u(__floats2half2_rn(a.x, a.y));
    o.y = h2u(__floats2half2_rn(a.z, a.w));
    o.z = h2u(__floats2half2_rn(b.x, b.y));
    o.w = h2u(__floats2half2_rn(b.z, b.w));
    ((uint4*)x16)[t] = o;
}

// ---------------------------------------------------------------------------
// CSR build
// ---------------------------------------------------------------------------
__global__ void deg_count_rank(const int* __restrict__ dst,
                               int* __restrict__ deg,
                               int* __restrict__ rank,
                               int n_edges)
{
    int e = blockIdx.x * blockDim.x + threadIdx.x;
    if (e < n_edges) rank[e] = atomicAdd(&deg[dst[e]], 1);
}

__global__ void scan1(const int* __restrict__ deg, int* __restrict__ pref,
                      int* __restrict__ chunkSum, int n)
{
    __shared__ int sT[256];
    int chunk = blockIdx.x;
    int base  = chunk * SCAN_CHUNK;
    int t     = threadIdx.x;

    int v[4], s = 0;
#pragma unroll
    for (int j = 0; j < 4; j++) {
        int idx = base + t * 4 + j;
        v[j] = (idx < n) ? deg[idx] : 0;
        s += v[j];
    }
    sT[t] = s;
    __syncthreads();
#pragma unroll
    for (int off = 1; off < 256; off <<= 1) {
        int y = (t >= off) ? sT[t - off] : 0;
        __syncthreads();
        sT[t] += y;
        __syncthreads();
    }
    int excl = sT[t] - s;
#pragma unroll
    for (int j = 0; j < 4; j++) {
        int idx = base + t * 4 + j;
        if (idx < n) pref[idx] = excl;
        excl += v[j];
    }
    if (t == 255) chunkSum[chunk] = sT[255];
}

__global__ void scan2b(int* __restrict__ rowptr,
                       const int* __restrict__ chunkSum, int n, int nchunks)
{
    __shared__ int sOff[MAX_CHUNKS];
    int t = threadIdx.x;
    if (t < nchunks) sOff[t] = chunkSum[t];
    __syncthreads();
#pragma unroll
    for (int off = 1; off < MAX_CHUNKS; off <<= 1) {
        int v = (t >= off && t < nchunks) ? sOff[t - off] : 0;
        __syncthreads();
        if (t < nchunks) sOff[t] += v;
        __syncthreads();
    }
    int i = blockIdx.x * blockDim.x + t;
    if (i < n) {
        int myChunk = i / SCAN_CHUNK;
        int off = (myChunk == 0) ? 0 : sOff[myChunk - 1];
        rowptr[i] += off;
    }
    if (i == 0) rowptr[n] = sOff[nchunks - 1];
}

// Atomic-free fill, 4 edges/thread with INDEPENDENT chains (MLP=4).
__global__ void csr_fill_rank(const int* __restrict__ src,
                              const int* __restrict__ dst,
                              const int* __restrict__ rank,
                              const int* __restrict__ rowptr,
                              int* __restrict__ col,
                              int n_edges)
{
    int t = blockIdx.x * blockDim.x + threadIdx.x;
    int base = t * 4;
    if (base + 3 < n_edges) {
        int4 d4 = *(const int4*)(dst + base);
        int4 r4 = *(const int4*)(rank + base);
        int4 s4 = *(const int4*)(src + base);
        int p0 = __ldg(rowptr + d4.x);
        int p1 = __ldg(rowptr + d4.y);
        int p2 = __ldg(rowptr + d4.z);
        int p3 = __ldg(rowptr + d4.w);
        col[p0 + r4.x] = s4.x;
        col[p1 + r4.y] = s4.y;
        col[p2 + r4.z] = s4.z;
        col[p3 + r4.w] = s4.w;
    } else {
        for (int e = base; e < n_edges; e++)
            col[rowptr[dst[e]] + rank[e]] = src[e];
    }
}

// ---------------------------------------------------------------------------
// fp16 CSR gather, C=32 (64B rows): one warp per node; 8 edges/iter.
// seg = lane&3 (8-channel 16B segment), sub = lane>>2 (edge within iter).
// fp32 accumulation; shfl reduce over sub lanes.
//   FUSE_OUT=false: outp[n,:] = raw sum          (fp32)
//   FUSE_OUT=true : outp[n,:] += sum/max(deg,1)  (out pre-init b2+hr)
// ---------------------------------------------------------------------------
template <bool FUSE_OUT>
__global__ __launch_bounds__(256)
void gather16(const __half* __restrict__ feat,
              const int* __restrict__ rowptr,
              const int* __restrict__ col,
              float* __restrict__ outp,
              int n_nodes)
{
    int node = (blockIdx.x * blockDim.x + threadIdx.x) >> 5;
    int lane = threadIdx.x & 31;
    if (node >= n_nodes) return;

    int beg = rowptr[node];
    int end = rowptr[node + 1];

    int sub = lane >> 2;   // 0..7
    int seg = lane & 3;    // 0..3

    float acc[8];
#pragma unroll
    for (int j = 0; j < 8; j++) acc[j] = 0.f;

    for (int i = beg; i < end; i += 8) {
        int cv = (lane < 8 && i + lane < end) ? __ldg(col + i + lane) : 0;
        int c  = __shfl_sync(0xffffffffu, cv, sub);
        if (i + sub < end) {
            uint4 v = *(const uint4*)(feat + (long long)c * 32 + seg * 8);
            float2 f0 = __half22float2(*reinterpret_cast<__half2*>(&v.x));
            float2 f1 = __half22float2(*reinterpret_cast<__half2*>(&v.y));
            float2 f2 = __half22float2(*reinterpret_cast<__half2*>(&v.z));
            float2 f3 = __half22float2(*reinterpret_cast<__half2*>(&v.w));
            acc[0] += f0.x; acc[1] += f0.y;
            acc[2] += f1.x; acc[3] += f1.y;
            acc[4] += f2.x; acc[5] += f2.y;
            acc[6] += f3.x; acc[7] += f3.y;
        }
    }
#pragma unroll
    for (int off = 4; off < 32; off <<= 1)
#pragma unroll
        for (int j = 0; j < 8; j++)
            acc[j] += __shfl_xor_sync(0xffffffffu, acc[j], off);

    if (lane < 4) {
        float* dstp = outp + (long long)node * 32 + seg * 8;
        if (FUSE_OUT) {
            float inv = 1.0f / fmaxf((float)(end - beg), 1.0f);
            float4 p0 = ((float4*)dstp)[0];
            float4 p1 = ((float4*)dstp)[1];
            p0.x += acc[0] * inv; p0.y += acc[1] * inv;
            p0.z += acc[2] * inv; p0.w += acc[3] * inv;
            p1.x += acc[4] * inv; p1.y += acc[5] * inv;
            p1.z += acc[6] * inv; p1.w += acc[7] * inv;
            ((float4*)dstp)[0] = p0;
            ((float4*)dstp)[1] = p1;
        } else {
            float4 o0 = {acc[0], acc[1], acc[2], acc[3]};
            float4 o1 = {acc[4], acc[5], acc[6], acc[7]};
            ((float4*)dstp)[0] = o0;
            ((float4*)dstp)[1] = o1;
        }
    }
}

// ---------------------------------------------------------------------------
// Tiled fused transform (R11/R13 structure; deg from rowptr).
// hw now written as fp16; out path unchanged fp32.
// ---------------------------------------------------------------------------
__global__ __launch_bounds__(256)
void transform_l1_tiled(const float* __restrict__ x,
                        const float* __restrict__ agg,
                        const int* __restrict__ rowptr,
                        const float* __restrict__ W1l,
                        const float* __restrict__ b1,
                        const float* __restrict__ W1r,
                        const float* __restrict__ W2l,
                        const float* __restrict__ b2,
                        const float* __restrict__ W2r,
                        __half* __restrict__ hw16,
                        float* __restrict__ outp,
                        int n_nodes)
{
    extern __shared__ __align__(16) float smem[];
    float* sAgg = smem;
    float* sX   = smem + IN_C * STRIDE;
    float* sH   = smem;                          // overlay
    float* sW1l = smem + HID_C * STRIDE;
    float* sW1r = sW1l + IN_C * HID_C;
    float* sW2  = sW1r + IN_C * HID_C;           // [W2l | W2r]
    float* sB   = sW2  + HID_C * 64;
    float* sB2  = sB   + HID_C;

    int tid  = threadIdx.x;
    int warp = tid >> 5;
    int lane = tid & 31;

    for (int i = tid * 4; i < IN_C * HID_C; i += 256 * 4) {
        *(float4*)&sW1l[i] = *(const float4*)&W1l[i];
        *(float4*)&sW1r[i] = *(const float4*)&W1r[i];
    }
    for (int i = tid * 4; i < HID_C * 64; i += 256 * 4) {
        int k = i >> 6, c = i & 63;
        float4 v = (c < 32) ? *(const float4*)&W2l[k * OUT_C + c]
                            : *(const float4*)&W2r[k * OUT_C + (c - 32)];
        *(float4*)&sW2[i] = v;
    }
    if (tid < HID_C) sB[tid] = b1[tid];
    if (tid < OUT_C) sB2[tid] = b2[tid];

    int nodeBase = blockIdx.x * NT;
    for (int i = tid; i < NT * 8; i += 256) {
        int node = i >> 3, kc = i & 7;
        int ng = nodeBase + node;
        float4 a = {0,0,0,0}, xv = {0,0,0,0};
        float inv = 0.0f;
        if (ng < n_nodes) {
            int deg = rowptr[ng + 1] - rowptr[ng];
            inv = 1.0f / fmaxf((float)deg, 1.0f);
            a  = *(const float4*)(agg + (long long)ng * IN_C + kc * 4);
            xv = *(const float4*)(x   + (long long)ng * IN_C + kc * 4);
        }
        int kb = kc * 4;
        sAgg[(kb + 0) * STRIDE + node] = a.x * inv;
        sAgg[(kb + 1) * STRIDE + node] = a.y * inv;
        sAgg[(kb + 2) * STRIDE + node] = a.z * inv;
        sAgg[(kb + 3) * STRIDE + node] = a.w * inv;
        sX  [(kb + 0) * STRIDE + node] = xv.x;
        sX  [(kb + 1) * STRIDE + node] = xv.y;
        sX  [(kb + 2) * STRIDE + node] = xv.z;
        sX  [(kb + 3) * STRIDE + node] = xv.w;
    }
    __syncthreads();

    const int cb = warp * 8;
    const int nb = lane * 4;

    unsigned long long acc[4][4];
#pragma unroll
    for (int n = 0; n < 4; n++)
#pragma unroll
        for (int p = 0; p < 4; p++) acc[n][p] = 0ull;

#pragma unroll
    for (int k = 0; k < IN_C; k++) {
        float4 av = *(const float4*)&sAgg[k * STRIDE + nb];
        float4 xv = *(const float4*)&sX  [k * STRIDE + nb];
        ulonglong2 wl0 = *(const ulonglong2*)&sW1l[k * HID_C + cb];
        ulonglong2 wl1 = *(const ulonglong2*)&sW1l[k * HID_C + cb + 4];
        ulonglong2 wr0 = *(const ulonglong2*)&sW1r[k * HID_C + cb];
        ulonglong2 wr1 = *(const ulonglong2*)&sW1r[k * HID_C + cb + 4];
        float avf[4] = {av.x, av.y, av.z, av.w};
        float xvf[4] = {xv.x, xv.y, xv.z, xv.w};
#pragma unroll
        for (int n = 0; n < 4; n++) {
            unsigned long long a2 = pack2(avf[n]);
            fma2(acc[n][0], a2, wl0.x); fma2(acc[n][1], a2, wl0.y);
            fma2(acc[n][2], a2, wl1.x); fma2(acc[n][3], a2, wl1.y);
            unsigned long long x2 = pack2(xvf[n]);
            fma2(acc[n][0], x2, wr0.x); fma2(acc[n][1], x2, wr0.y);
            fma2(acc[n][2], x2, wr1.x); fma2(acc[n][3], x2, wr1.y);
        }
    }
    __syncthreads();

#pragma unroll
    for (int c = 0; c < 8; c += 2) {
        float2 p0 = unpack2(acc[0][c / 2]);
        float2 p1 = unpack2(acc[1][c / 2]);
        float2 p2 = unpack2(acc[2][c / 2]);
        float2 p3 = unpack2(acc[3][c / 2]);
        float b0 = sB[cb + c], b1v = sB[cb + c + 1];
        float4 v0 = {fmaxf(p0.x + b0, 0.f), fmaxf(p1.x + b0, 0.f),
                     fmaxf(p2.x + b0, 0.f), fmaxf(p3.x + b0, 0.f)};
        float4 v1 = {fmaxf(p0.y + b1v, 0.f), fmaxf(p1.y + b1v, 0.f),
                     fmaxf(p2.y + b1v, 0.f), fmaxf(p3.y + b1v, 0.f)};
        *(float4*)&sH[(cb + c)     * STRIDE + nb] = v0;
        *(float4*)&sH[(cb + c + 1) * STRIDE + nb] = v1;
    }
    __syncthreads();

    unsigned long long acc2[4][4];
#pragma unroll
    for (int n = 0; n < 4; n++)
#pragma unroll
        for (int p = 0; p < 4; p++) acc2[n][p] = 0ull;

#pragma unroll 8
    for (int k = 0; k < HID_C; k++) {
        float4 hv = *(const float4*)&sH[k * STRIDE + nb];
        ulonglong2 w0 = *(const ulonglong2*)&sW2[k * 64 + cb];
        ulonglong2 w1 = *(const ulonglong2*)&sW2[k * 64 + cb + 4];
        float hvf[4] = {hv.x, hv.y, hv.z, hv.w};
#pragma unroll
        for (int n = 0; n < 4; n++) {
            unsigned long long h2 = pack2(hvf[n]);
            fma2(acc2[n][0], h2, w0.x); fma2(acc2[n][1], h2, w0.y);
            fma2(acc2[n][2], h2, w1.x); fma2(acc2[n][3], h2, w1.y);
        }
    }

    if (cb < 32) {
        // hw path: write fp16 (8 channels = 16B per node)
#pragma unroll
        for (int n = 0; n < 4; n++) {
            int node = nodeBase + nb + n;
            if (node < n_nodes) {
                float2 q0 = unpack2(acc2[n][0]);
                float2 q1 = unpack2(acc2[n][1]);
                float2 q2 = unpack2(acc2[n][2]);
                float2 q3 = unpack2(acc2[n][3]);
                uint4 o;
                o.x = h2u(__floats2half2_rn(q0.x, q0.y));
                o.y = h2u(__floats2half2_rn(q1.x, q1.y));
                o.z = h2u(__floats2half2_rn(q2.x, q2.y));
                o.w = h2u(__floats2half2_rn(q3.x, q3.y));
                *(uint4*)(hw16 + (long long)node * OUT_C + cb) = o;
            }
        }
    } else {
        // out path: fp32, + b2 (gather2 adds the mean term onto it)
        int coff = cb - 32;
        float add[8];
#pragma unroll
        for (int j = 0; j < 8; j++) add[j] = sB2[coff + j];
#pragma unroll
        for (int n = 0; n < 4; n++) {
            int node = nodeBase + nb + n;
            if (node < n_nodes) {
                float2 q0 = unpack2(acc2[n][0]);
                float2 q1 = unpack2(acc2[n][1]);
                float2 q2 = unpack2(acc2[n][2]);
                float2 q3 = unpack2(acc2[n][3]);
                float4 o0 = {q0.x + add[0], q0.y + add[1], q1.x + add[2], q1.y + add[3]};
                float4 o1 = {q2.x + add[4], q2.y + add[5], q3.x + add[6], q3.y + add[7]};
                *(float4*)(outp + (long long)node * OUT_C + coff)     = o0;
                *(float4*)(outp + (long long)node * OUT_C + coff + 4) = o1;
            }
        }
    }
}

// ---------------------------------------------------------------------------
// Launch (single stream — R14 lesson: overlap of LTS-bound phases is a wash)
// ---------------------------------------------------------------------------
extern "C" void kernel_launch(void* const* d_in, const int* in_sizes, int n_in,
                              void* d_out, int out_size)
{
    const float* x    = (const float*)d_in[0];
    const int*   ei   = (const int*)d_in[1];     // [2, E] int32
    const float* W1l  = (const float*)d_in[2];
    const float* b1   = (const float*)d_in[3];
    const float* W1r  = (const float*)d_in[4];
    const float* W2l  = (const float*)d_in[5];
    const float* b2   = (const float*)d_in[6];
    const float* W2r  = (const float*)d_in[7];
    float*       out  = (float*)d_out;

    const int n_nodes = in_sizes[0] / IN_C;
    const int n_edges = in_sizes[1] / 2;
    const int nchunks = (n_nodes + SCAN_CHUNK - 1) / SCAN_CHUNK;

    const int* src = ei;
    const int* dst = ei + n_edges;

    float *agg1; __half *x16, *hw16;
    int *deg, *rowptr, *rank, *col, *chunkSum;
    cudaGetSymbolAddress((void**)&agg1,     g_agg1);
    cudaGetSymbolAddress((void**)&x16,      g_x16);
    cudaGetSymbolAddress((void**)&hw16,     g_hw16);
    cudaGetSymbolAddress((void**)&deg,      g_deg);
    cudaGetSymbolAddress((void**)&rowptr,   g_rowptr);
    cudaGetSymbolAddress((void**)&rank,     g_rank);
    cudaGetSymbolAddress((void**)&col,      g_col);
    cudaGetSymbolAddress((void**)&chunkSum, g_chunkSum);

    // x -> fp16 (cheap; independent of everything below)
    {
        int n8 = n_nodes * IN_C / 8;
        cvt_x16<<<(n8 + 255) / 256, 256>>>(x, x16, n8);
    }

    // --- CSR build ---
    cudaMemsetAsync(deg, 0, (size_t)n_nodes * sizeof(int));
    deg_count_rank<<<(n_edges + 255) / 256, 256>>>(dst, deg, rank, n_edges);
    scan1<<<nchunks, 256>>>(deg, rowptr, chunkSum, n_nodes);
    scan2b<<<(n_nodes + 255) / 256, 256>>>(rowptr, chunkSum, n_nodes, nchunks);
    {
        int t = (n_edges + 3) / 4;
        csr_fill_rank<<<(t + 255) / 256, 256>>>(src, dst, rank, rowptr, col, n_edges);
    }

    const int gather_blocks = (n_nodes * 32 + 255) / 256;

    // Layer 1 aggregate: raw sums from fp16 x
    gather16<false><<<gather_blocks, 256>>>(x16, rowptr, col, agg1, n_nodes);

    // Tiled fused transform -> hw16, out(=b2+hr)
    {
        const int smem_bytes = (HID_C * STRIDE + 2 * IN_C * HID_C
                              + HID_C * 64 + HID_C + OUT_C) * (int)sizeof(float);
        static bool attr_set = false;
        if (!attr_set) {
            cudaFuncSetAttribute(transform_l1_tiled,
                                 cudaFuncAttributeMaxDynamicSharedMemorySize,
                                 smem_bytes);
            attr_set = true;
        }
        int blocks = (n_nodes + NT - 1) / NT;
        transform_l1_tiled<<<blocks, 256, smem_bytes>>>(
            x, agg1, rowptr, W1l, b1, W1r, W2l, b2, W2r, hw16, out, n_nodes);
    }

    // Layer 2: fused fp16 gather + final combine
    gather16<true><<<gather_blocks, 256>>>(hw16, rowptr, col, out, n_nodes);
}

// round 17
// speedup vs baseline: 1.1373x; 1.1373x over previous
#include <cuda_runtime.h>
#include <cstdint>

#define MAX_NODES 100000
#define MAX_EDGES 1600000
#define IN_C  32
#define HID_C 64
#define OUT_C 32
#define NT 128
#define STRIDE 132
#define SCAN_CHUNK 1024
#define MAX_CHUNKS 128

// Scratch (__device__ globals: allocation-free rule)
__device__ __align__(16) float g_agg1[MAX_NODES * IN_C];   // raw sums
__device__ __align__(16) float g_hw  [MAX_NODES * OUT_C];  // relu(h) @ W2_l
__device__ int g_deg     [MAX_NODES];
__device__ int g_rowptr  [MAX_NODES + 1];
__device__ int g_rank    [MAX_EDGES];
__device__ int g_col     [MAX_EDGES];
__device__ int g_chunkSum[MAX_CHUNKS];
__device__ int g_chunkOff[MAX_CHUNKS];

// ---------------------------------------------------------------------------
// Packed f32x2 helpers (Blackwell FFMA2)
// ---------------------------------------------------------------------------
__device__ __forceinline__ void fma2(unsigned long long& d,
                                     unsigned long long a,
                                     unsigned long long b)
{
    asm("fma.rn.f32x2 %0, %1, %2, %0;" : "+l"(d) : "l"(a), "l"(b));
}
__device__ __forceinline__ unsigned long long pack2(float v)
{
    unsigned long long r;
    asm("mov.b64 %0, {%1, %1};" : "=l"(r) : "r"(__float_as_uint(v)));
    return r;
}
__device__ __forceinline__ float2 unpack2(unsigned long long v)
{
    float2 f;
    asm("mov.b64 {%0, %1}, %2;" : "=f"(f.x), "=f"(f.y) : "l"(v));
    return f;
}

// ---------------------------------------------------------------------------
// CSR build
// ---------------------------------------------------------------------------
__global__ void deg_count_rank(const int* __restrict__ dst,
                               int* __restrict__ deg,
                               int* __restrict__ rank,
                               int n_edges)
{
    int e = blockIdx.x * blockDim.x + threadIdx.x;
    if (e < n_edges) rank[e] = atomicAdd(&deg[dst[e]], 1);
}

__global__ void scan1(const int* __restrict__ deg, int* __restrict__ pref,
                      int* __restrict__ chunkSum, int n)
{
    __shared__ int sT[256];
    int chunk = blockIdx.x;
    int base  = chunk * SCAN_CHUNK;
    int t     = threadIdx.x;

    int v[4], s = 0;
#pragma unroll
    for (int j = 0; j < 4; j++) {
        int idx = base + t * 4 + j;
        v[j] = (idx < n) ? deg[idx] : 0;
        s += v[j];
    }
    sT[t] = s;
    __syncthreads();
#pragma unroll
    for (int off = 1; off < 256; off <<= 1) {
        int y = (t >= off) ? sT[t - off] : 0;
        __syncthreads();
        sT[t] += y;
        __syncthreads();
    }
    int excl = sT[t] - s;
#pragma unroll
    for (int j = 0; j < 4; j++) {
        int idx = base + t * 4 + j;
        if (idx < n) pref[idx] = excl;
        excl += v[j];
    }
    if (t == 255) chunkSum[chunk] = sT[255];
}

// Single-block inclusive scan of chunk sums (98 elems)
__global__ void scan_chunks(const int* __restrict__ chunkSum,
                            int* __restrict__ chunkOff, int nchunks)
{
    __shared__ int sS[MAX_CHUNKS];
    int t = threadIdx.x;
    if (t < nchunks) sS[t] = chunkSum[t];
    __syncthreads();
#pragma unroll
    for (int off = 1; off < MAX_CHUNKS; off <<= 1) {
        int v = (t >= off && t < nchunks) ? sS[t - off] : 0;
        __syncthreads();
        if (t < nchunks) sS[t] += v;
        __syncthreads();
    }
    if (t < nchunks) chunkOff[t] = sS[t];
}

// Trivial add of chunk offsets; close rowptr.
__global__ void scan_add(int* __restrict__ rowptr,
                         const int* __restrict__ chunkOff, int n, int nchunks)
{
    int i = blockIdx.x * blockDim.x + threadIdx.x;
    if (i < n) {
        int myChunk = i / SCAN_CHUNK;
        int off = (myChunk == 0) ? 0 : __ldg(chunkOff + myChunk - 1);
        rowptr[i] += off;
    }
    if (i == 0) rowptr[n] = __ldg(chunkOff + nchunks - 1);
}

// Atomic-free fill, 4 edges/thread with INDEPENDENT chains (MLP=4).
__global__ void csr_fill_rank(const int* __restrict__ src,
                              const int* __restrict__ dst,
                              const int* __restrict__ rank,
                              const int* __restrict__ rowptr,
                              int* __restrict__ col,
                              int n_edges)
{
    int t = blockIdx.x * blockDim.x + threadIdx.x;
    int base = t * 4;
    if (base + 3 < n_edges) {
        int4 d4 = *(const int4*)(dst + base);
        int4 r4 = *(const int4*)(rank + base);
        int4 s4 = *(const int4*)(src + base);
        int p0 = __ldg(rowptr + d4.x);
        int p1 = __ldg(rowptr + d4.y);
        int p2 = __ldg(rowptr + d4.z);
        int p3 = __ldg(rowptr + d4.w);
        col[p0 + r4.x] = s4.x;
        col[p1 + r4.y] = s4.y;
        col[p2 + r4.z] = s4.z;
        col[p3 + r4.w] = s4.w;
    } else {
        for (int e = base; e < n_edges; e++)
            col[rowptr[dst[e]] + rank[e]] = src[e];
    }
}

// ---------------------------------------------------------------------------
// CSR gather v2, C=32: FOUR nodes per warp, 8 lanes per node, each lane owns
// one float4 segment exclusively -> NO cross-lane reduce, no shfl at all.
// col loads are same-address within a node's 8-lane group (sector broadcast).
// Unroll-2 edge loop for MLP.
//   FUSE_OUT=false: outp[n,:] = raw sum
//   FUSE_OUT=true : outp[n,:] += sum/max(deg,1)  (out pre-init b2+hr)
// ---------------------------------------------------------------------------
template <bool FUSE_OUT>
__global__ __launch_bounds__(256)
void gather32(const float* __restrict__ feat,
              const int* __restrict__ rowptr,
              const int* __restrict__ col,
              float* __restrict__ outp,
              int n_nodes)
{
    int warp = (blockIdx.x * blockDim.x + threadIdx.x) >> 5;
    int lane = threadIdx.x & 31;
    int node = warp * 4 + (lane >> 3);
    int seg  = lane & 7;
    if (node >= n_nodes) return;

    int beg = __ldg(rowptr + node);
    int end = __ldg(rowptr + node + 1);

    float4 acc = {0.f, 0.f, 0.f, 0.f};
    int e = beg;
    for (; e + 1 < end; e += 2) {
        int c0 = __ldg(col + e);
        int c1 = __ldg(col + e + 1);
        float4 v0 = *(const float4*)(feat + (long long)c0 * 32 + seg * 4);
        float4 v1 = *(const float4*)(feat + (long long)c1 * 32 + seg * 4);
        acc.x += v0.x + v1.x; acc.y += v0.y + v1.y;
        acc.z += v0.z + v1.z; acc.w += v0.w + v1.w;
    }
    if (e < end) {
        int c0 = __ldg(col + e);
        float4 v0 = *(const float4*)(feat + (long long)c0 * 32 + seg * 4);
        acc.x += v0.x; acc.y += v0.y; acc.z += v0.z; acc.w += v0.w;
    }

    float* dstp = outp + (long long)node * 32 + seg * 4;
    if (FUSE_OUT) {
        float inv = 1.0f / fmaxf((float)(end - beg), 1.0f);
        float4 prev = *(const float4*)dstp;
        float4 o;
        o.x = acc.x * inv + prev.x;
        o.y = acc.y * inv + prev.y;
        o.z = acc.z * inv + prev.z;
        o.w = acc.w * inv + prev.w;
        *(float4*)dstp = o;
    } else {
        *(float4*)dstp = acc;
    }
}

// ---------------------------------------------------------------------------
// Tiled fused transform (R13/R15 structure; deg from rowptr)
// ---------------------------------------------------------------------------
__global__ __launch_bounds__(256)
void transform_l1_tiled(const float* __restrict__ x,
                        const float* __restrict__ agg,
                        const int* __restrict__ rowptr,
                        const float* __restrict__ W1l,
                        const float* __restrict__ b1,
                        const float* __restrict__ W1r,
                        const float* __restrict__ W2l,
                        const float* __restrict__ b2,
                        const float* __restrict__ W2r,
                        float* __restrict__ hw,
                        float* __restrict__ outp,
                        int n_nodes)
{
    extern __shared__ __align__(16) float smem[];
    float* sAgg = smem;
    float* sX   = smem + IN_C * STRIDE;
    float* sH   = smem;                          // overlay
    float* sW1l = smem + HID_C * STRIDE;
    float* sW1r = sW1l + IN_C * HID_C;
    float* sW2  = sW1r + IN_C * HID_C;           // [W2l | W2r]
    float* sB   = sW2  + HID_C * 64;
    float* sB2  = sB   + HID_C;

    int tid  = threadIdx.x;
    int warp = tid >> 5;
    int lane = tid & 31;

    for (int i = tid * 4; i < IN_C * HID_C; i += 256 * 4) {
        *(float4*)&sW1l[i] = *(const float4*)&W1l[i];
        *(float4*)&sW1r[i] = *(const float4*)&W1r[i];
    }
    for (int i = tid * 4; i < HID_C * 64; i += 256 * 4) {
        int k = i >> 6, c = i & 63;
        float4 v = (c < 32) ? *(const float4*)&W2l[k * OUT_C + c]
                            : *(const float4*)&W2r[k * OUT_C + (c - 32)];
        *(float4*)&sW2[i] = v;
    }
    if (tid < HID_C) sB[tid] = b1[tid];
    if (tid < OUT_C) sB2[tid] = b2[tid];

    int nodeBase = blockIdx.x * NT;
    for (int i = tid; i < NT * 8; i += 256) {
        int node = i >> 3, kc = i & 7;
        int ng = nodeBase + node;
        float4 a = {0,0,0,0}, xv = {0,0,0,0};
        float inv = 0.0f;
        if (ng < n_nodes) {
            int deg = rowptr[ng + 1] - rowptr[ng];
            inv = 1.0f / fmaxf((float)deg, 1.0f);
            a  = *(const float4*)(agg + (long long)ng * IN_C + kc * 4);
            xv = *(const float4*)(x   + (long long)ng * IN_C + kc * 4);
        }
        int kb = kc * 4;
        sAgg[(kb + 0) * STRIDE + node] = a.x * inv;
        sAgg[(kb + 1) * STRIDE + node] = a.y * inv;
        sAgg[(kb + 2) * STRIDE + node] = a.z * inv;
        sAgg[(kb + 3) * STRIDE + node] = a.w * inv;
        sX  [(kb + 0) * STRIDE + node] = xv.x;
        sX  [(kb + 1) * STRIDE + node] = xv.y;
        sX  [(kb + 2) * STRIDE + node] = xv.z;
        sX  [(kb + 3) * STRIDE + node] = xv.w;
    }
    __syncthreads();

    const int cb = warp * 8;
    const int nb = lane * 4;

    unsigned long long acc[4][4];
#pragma unroll
    for (int n = 0; n < 4; n++)
#pragma unroll
        for (int p = 0; p < 4; p++) acc[n][p] = 0ull;

#pragma unroll
    for (int k = 0; k < IN_C; k++) {
        float4 av = *(const float4*)&sAgg[k * STRIDE + nb];
        float4 xv = *(const float4*)&sX  [k * STRIDE + nb];
        ulonglong2 wl0 = *(const ulonglong2*)&sW1l[k * HID_C + cb];
        ulonglong2 wl1 = *(const ulonglong2*)&sW1l[k * HID_C + cb + 4];
        ulonglong2 wr0 = *(const ulonglong2*)&sW1r[k * HID_C + cb];
        ulonglong2 wr1 = *(const ulonglong2*)&sW1r[k * HID_C + cb + 4];
        float avf[4] = {av.x, av.y, av.z, av.w};
        float xvf[4] = {xv.x, xv.y, xv.z, xv.w};
#pragma unroll
        for (int n = 0; n < 4; n++) {
            unsigned long long a2 = pack2(avf[n]);
            fma2(acc[n][0], a2, wl0.x); fma2(acc[n][1], a2, wl0.y);
            fma2(acc[n][2], a2, wl1.x); fma2(acc[n][3], a2, wl1.y);
            unsigned long long x2 = pack2(xvf[n]);
            fma2(acc[n][0], x2, wr0.x); fma2(acc[n][1], x2, wr0.y);
            fma2(acc[n][2], x2, wr1.x); fma2(acc[n][3], x2, wr1.y);
        }
    }
    __syncthreads();

#pragma unroll
    for (int c = 0; c < 8; c += 2) {
        float2 p0 = unpack2(acc[0][c / 2]);
        float2 p1 = unpack2(acc[1][c / 2]);
        float2 p2 = unpack2(acc[2][c / 2]);
        float2 p3 = unpack2(acc[3][c / 2]);
        float b0 = sB[cb + c], b1v = sB[cb + c + 1];
        float4 v0 = {fmaxf(p0.x + b0, 0.f), fmaxf(p1.x + b0, 0.f),
                     fmaxf(p2.x + b0, 0.f), fmaxf(p3.x + b0, 0.f)};
        float4 v1 = {fmaxf(p0.y + b1v, 0.f), fmaxf(p1.y + b1v, 0.f),
                     fmaxf(p2.y + b1v, 0.f), fmaxf(p3.y + b1v, 0.f)};
        *(float4*)&sH[(cb + c)     * STRIDE + nb] = v0;
        *(float4*)&sH[(cb + c + 1) * STRIDE + nb] = v1;
    }
    __syncthreads();

    unsigned long long acc2[4][4];
#pragma unroll
    for (int n = 0; n < 4; n++)
#pragma unroll
        for (int p = 0; p < 4; p++) acc2[n][p] = 0ull;

#pragma unroll 8
    for (int k = 0; k < HID_C; k++) {
        float4 hv = *(const float4*)&sH[k * STRIDE + nb];
        ulonglong2 w0 = *(const ulonglong2*)&sW2[k * 64 + cb];
        ulonglong2 w1 = *(const ulonglong2*)&sW2[k * 64 + cb + 4];
        float hvf[4] = {hv.x, hv.y, hv.z, hv.w};
#pragma unroll
        for (int n = 0; n < 4; n++) {
            unsigned long long h2 = pack2(hvf[n]);
            fma2(acc2[n][0], h2, w0.x); fma2(acc2[n][1], h2, w0.y);
            fma2(acc2[n][2], h2, w1.x); fma2(acc2[n][3], h2, w1.y);
        }
    }

    bool to_out = (cb >= 32);
    float* basep = to_out ? outp : hw;
    int coff = to_out ? cb - 32 : cb;
    float add[8];
#pragma unroll
    for (int j = 0; j < 8; j++) add[j] = to_out ? sB2[coff + j] : 0.f;
#pragma unroll
    for (int n = 0; n < 4; n++) {
        int node = nodeBase + nb + n;
        if (node < n_nodes) {
            float2 q0 = unpack2(acc2[n][0]);
            float2 q1 = unpack2(acc2[n][1]);
            float2 q2 = unpack2(acc2[n][2]);
            float2 q3 = unpack2(acc2[n][3]);
            float4 o0 = {q0.x + add[0], q0.y + add[1], q1.x + add[2], q1.y + add[3]};
            float4 o1 = {q2.x + add[4], q2.y + add[5], q3.x + add[6], q3.y + add[7]};
            *(float4*)(basep + (long long)node * OUT_C + coff)     = o0;
            *(float4*)(basep + (long long)node * OUT_C + coff + 4) = o1;
        }
    }
}

// ---------------------------------------------------------------------------
// Launch
// ---------------------------------------------------------------------------
extern "C" void kernel_launch(void* const* d_in, const int* in_sizes, int n_in,
                              void* d_out, int out_size)
{
    const float* x    = (const float*)d_in[0];
    const int*   ei   = (const int*)d_in[1];     // [2, E] int32
    const float* W1l  = (const float*)d_in[2];
    const float* b1   = (const float*)d_in[3];
    const float* W1r  = (const float*)d_in[4];
    const float* W2l  = (const float*)d_in[5];
    const float* b2   = (const float*)d_in[6];
    const float* W2r  = (const float*)d_in[7];
    float*       out  = (float*)d_out;

    const int n_nodes = in_sizes[0] / IN_C;
    const int n_edges = in_sizes[1] / 2;
    const int nchunks = (n_nodes + SCAN_CHUNK - 1) / SCAN_CHUNK;

    const int* src = ei;
    const int* dst = ei + n_edges;

    float *agg1, *hw;
    int *deg, *rowptr, *rank, *col, *chunkSum, *chunkOff;
    cudaGetSymbolAddress((void**)&agg1,     g_agg1);
    cudaGetSymbolAddress((void**)&hw,       g_hw);
    cudaGetSymbolAddress((void**)&deg,      g_deg);
    cudaGetSymbolAddress((void**)&rowptr,   g_rowptr);
    cudaGetSymbolAddress((void**)&rank,     g_rank);
    cudaGetSymbolAddress((void**)&col,      g_col);
    cudaGetSymbolAddress((void**)&chunkSum, g_chunkSum);
    cudaGetSymbolAddress((void**)&chunkOff, g_chunkOff);

    // --- CSR build (rank-based, atomic-free fill) ---
    cudaMemsetAsync(deg, 0, (size_t)n_nodes * sizeof(int));
    deg_count_rank<<<(n_edges + 255) / 256, 256>>>(dst, deg, rank, n_edges);
    scan1<<<nchunks, 256>>>(deg, rowptr, chunkSum, n_nodes);
    scan_chunks<<<1, MAX_CHUNKS>>>(chunkSum, chunkOff, nchunks);
    scan_add<<<(n_nodes + 255) / 256, 256>>>(rowptr, chunkOff, n_nodes, nchunks);
    {
        int t = (n_edges + 3) / 4;
        csr_fill_rank<<<(t + 255) / 256, 256>>>(src, dst, rank, rowptr, col, n_edges);
    }

    // Gather grid: 4 nodes/warp
    const int gwarps = (n_nodes + 3) / 4;
    const int gather_blocks = (gwarps * 32 + 255) / 256;

    // Layer 1 aggregate: raw sums
    gather32<false><<<gather_blocks, 256>>>(x, rowptr, col, agg1, n_nodes);

    // Tiled fused transform -> hw, out(=b2+hr)
    {
        const int smem_bytes = (HID_C * STRIDE + 2 * IN_C * HID_C
                              + HID_C * 64 + HID_C + OUT_C) * (int)sizeof(float);
        static bool attr_set = false;
        if (!attr_set) {
            cudaFuncSetAttribute(transform_l1_tiled,
                                 cudaFuncAttributeMaxDynamicSharedMemorySize,
                                 smem_bytes);
            attr_set = true;
        }
        int blocks = (n_nodes + NT - 1) / NT;
        transform_l1_tiled<<<blocks, 256, smem_bytes>>>(
            x, agg1, rowptr, W1l, b1, W1r, W2l, b2, W2r, hw, out, n_nodes);
    }

    // Layer 2: fused gather + final combine
    gather32<true><<<gather_blocks, 256>>>(hw, rowptr, col, out, n_nodes);
}